// round 3
// baseline (speedup 1.0000x reference)
#include <cuda_runtime.h>

#define BB 128
#define TT 1024
#define VV 192
#define NTHREADS 384
#define HALF 96
#define NWARPS 12

__device__ __forceinline__ unsigned long long pack2(float lo, float hi) {
    unsigned long long r;
    asm("mov.b64 %0, {%1, %2};" : "=l"(r) : "f"(lo), "f"(hi));
    return r;
}
__device__ __forceinline__ void unpack2(unsigned long long v, float& lo, float& hi) {
    asm("mov.b64 {%0, %1}, %2;" : "=f"(lo), "=f"(hi) : "l"(v));
}
__device__ __forceinline__ void ffma2(unsigned long long& acc,
                                      unsigned long long a, unsigned long long b) {
    asm("fma.rn.f32x2 %0, %1, %2, %0;" : "+l"(acc) : "l"(a), "l"(b));
}

__global__ __launch_bounds__(NTHREADS, 1)
void crf_loss_kernel(const float* __restrict__ em,
                     const int* __restrict__ tags,
                     const int* __restrict__ mask,
                     const float* __restrict__ trans,
                     const float* __restrict__ start_t,
                     const float* __restrict__ end_t,
                     float* __restrict__ out)
{
    __shared__ __align__(16) float s_p[2][VV];   // double-buffered exp(alpha - M)
    __shared__ float s_d[2];                     // double-buffered normalizer increment
    __shared__ int   s_mask[TT];
    __shared__ float s_red[NWARPS];
    __shared__ int   s_ired[NWARPS];
    __shared__ float s_num;
    __shared__ float s_seqlen;

    const int b    = blockIdx.x;
    const int tid  = threadIdx.x;
    const int lane = tid & 31;
    const int wid  = tid >> 5;
    const int j    = tid >> 1;      // output column (pairs of adjacent lanes share j)
    const int h    = tid & 1;       // which K-half this thread owns

    const float* emB = em   + (size_t)b * TT * VV;
    const int*   tgB = tags + (size_t)b * TT;
    const int*   mkB = mask + (size_t)b * TT;

    // ---------------- expT half-column, packed f32x2, into registers ----------------
    unsigned long long col2[HALF / 2];
    #pragma unroll
    for (int i = 0; i < HALF; i += 2) {
        float e0 = __expf(trans[(h * HALF + i    ) * VV + j]);
        float e1 = __expf(trans[(h * HALF + i + 1) * VV + j]);
        col2[i / 2] = pack2(e0, e1);
    }

    // ---------------- mask to smem ----------------
    for (int t = tid; t < TT; t += NTHREADS) s_mask[t] = mkB[t];

    // ---------------- gold score + mask sum ----------------
    float gsum = 0.f;
    int   msum = 0;
    for (int t = tid; t < TT; t += NTHREADS) {
        int mk = mkB[t];
        msum += mk;
        if (t >= 1 && mk) {
            int tg = tgB[t];
            int tp = tgB[t - 1];
            gsum += emB[t * VV + tg] + trans[tp * VV + tg];
        }
    }
    #pragma unroll
    for (int o = 16; o > 0; o >>= 1) {
        gsum += __shfl_xor_sync(0xffffffffu, gsum, o);
        msum += __shfl_xor_sync(0xffffffffu, msum, o);
    }
    if (lane == 0) { s_red[wid] = gsum; s_ired[wid] = msum; }
    __syncthreads();
    if (tid == 0) {
        float g = 0.f; int mtot = 0;
        #pragma unroll
        for (int w = 0; w < NWARPS; w++) { g += s_red[w]; mtot += s_ired[w]; }
        int tag0  = tgB[0];
        float num = start_t[tag0] + emB[tag0] + g;
        int last  = mtot - 1; if (last < 0) last = 0;
        num += end_t[tgB[last]];
        s_num    = num;
        s_seqlen = fmaxf((float)mtot, 1.0f);
    }

    // ---------------- init: alpha0, block max M0, p0 ----------------
    float a0 = start_t[j] + emB[j];
    float wm = a0;
    #pragma unroll
    for (int o = 16; o > 0; o >>= 1)
        wm = fmaxf(wm, __shfl_xor_sync(0xffffffffu, wm, o));
    __syncthreads();                       // protects s_red reuse
    if (lane == 0) s_red[wid] = wm;
    __syncthreads();
    float M = s_red[0];
    #pragma unroll
    for (int w = 1; w < NWARPS; w++) M = fmaxf(M, s_red[w]);

    float p = __expf(a0 - M);              // this thread's current p value
    if (h == 0) s_p[0][j] = p;
    if (tid == 0) s_d[0] = a0 - M;         // d_1 estimate = beta_0(0)

    float emit_next = emB[VV + j];         // t = 1 emission

    // thread-0 estimator state
    float lr_prev = 0.f, d_prev = 0.f, beta0 = a0 - M;

    // ---------------- forward recursion: ONE sync per step ----------------
    #pragma unroll 2
    for (int t = 1; t < TT; t++) {
        const int cur = (t - 1) & 1, nxt = t & 1;
        __syncthreads();

        const float d       = s_d[cur];
        const float emit_c  = emit_next;
        const int   mk      = s_mask[t];
        // early (off critical path): exp factors for this step
        const float w_emit  = __expf(emit_c - d);   // used when mask=1
        const float w_keep  = __expf(-d);           // used when mask=0
        // prefetch next emission
        {
            int tn = (t + 1 < TT) ? (t + 1) : (TT - 1);
            emit_next = emB[tn * VV + j];
        }

        // mat-vec partial over this thread's 96-element half-column (packed)
        const double2* p2 = (const double2*)(s_p[cur] + h * HALF);
        unsigned long long ac0 = 0ull, ac1 = 0ull, ac2 = 0ull, ac3 = 0ull;
        #pragma unroll
        for (int q = 0; q < HALF / 4; q += 2) {
            double2 v  = p2[q];
            double2 v2 = p2[q + 1];
            ffma2(ac0, __double_as_longlong(v.x),  col2[2 * q + 0]);
            ffma2(ac1, __double_as_longlong(v.y),  col2[2 * q + 1]);
            ffma2(ac2, __double_as_longlong(v2.x), col2[2 * q + 2]);
            ffma2(ac3, __double_as_longlong(v2.y), col2[2 * q + 3]);
        }
        float l0, h0, l1, h1, l2, h2, l3, h3;
        unpack2(ac0, l0, h0); unpack2(ac1, l1, h1);
        unpack2(ac2, l2, h2); unpack2(ac3, l3, h3);
        float s_half = ((l0 + h0) + (l1 + h1)) + ((l2 + h2) + (l3 + h3));
        float s = s_half + __shfl_xor_sync(0xffffffffu, s_half, 1);

        // p update: short tail (FMUL + STS); log kept off the main path
        float p_new = mk ? (s * w_emit) : (p * w_keep);
        p = p_new;
        M += d;
        if (h == 0) s_p[nxt][j] = p_new;

        if (tid == 0) {
            float lr = __logf(s) + emit_c;             // na_0 - M_{t-1}
            beta0 = mk ? (lr - d) : (beta0 - d);
            float g_est = lr - lr_prev + d_prev;       // last step's true growth
            s_d[nxt] = beta0 + g_est;
            lr_prev = lr; d_prev = d;
        }
    }

    // ---------------- final lse(alpha + end_trans) ----------------
    __syncthreads();
    float beta = __logf(p);                      // recover normalized alpha
    float v = (h == 0) ? (beta + end_t[j]) : -3.0e38f;
    float wm2 = v;
    #pragma unroll
    for (int o = 16; o > 0; o >>= 1)
        wm2 = fmaxf(wm2, __shfl_xor_sync(0xffffffffu, wm2, o));
    if (lane == 0) s_red[wid] = wm2;
    __syncthreads();
    float m2 = s_red[0];
    #pragma unroll
    for (int w = 1; w < NWARPS; w++) m2 = fmaxf(m2, s_red[w]);

    float e = (h == 0) ? __expf(v - m2) : 0.f;
    #pragma unroll
    for (int o = 16; o > 0; o >>= 1)
        e += __shfl_xor_sync(0xffffffffu, e, o);
    __syncthreads();                             // protects s_red reuse
    if (lane == 0) s_red[wid] = e;
    __syncthreads();

    if (tid == 0) {
        float ssum = 0.f;
        #pragma unroll
        for (int w = 0; w < NWARPS; w++) ssum += s_red[w];
        float logden = M + m2 + logf(ssum + 1e-8f);
        out[b] = (logden - s_num) / s_seqlen;
    }
}

extern "C" void kernel_launch(void* const* d_in, const int* in_sizes, int n_in,
                              void* d_out, int out_size)
{
    const float* em    = (const float*)d_in[0];
    const int*   tags  = (const int*)d_in[1];
    const int*   mask  = (const int*)d_in[2];
    const float* trans = (const float*)d_in[3];
    const float* st    = (const float*)d_in[4];
    const float* en    = (const float*)d_in[5];
    float* out = (float*)d_out;

    crf_loss_kernel<<<BB, NTHREADS>>>(em, tags, mask, trans, st, en, out);
}

// round 4
// speedup vs baseline: 1.4778x; 1.4778x over previous
#include <cuda_runtime.h>

#define BB 128
#define TT 1024
#define VV 192
#define NTHREADS 384
#define NWARPS 12
#define RROWS 24          // rows per group
#define RSTRIDE 28        // padded region stride in floats (bank-spread: 28g mod 32 distinct)
#define NGROUPS 8

__device__ __forceinline__ void ffma2(unsigned long long& acc,
                                      unsigned long long a, unsigned long long b) {
    asm("fma.rn.f32x2 %0, %1, %2, %0;" : "+l"(acc) : "l"(a), "l"(b));
}
__device__ __forceinline__ unsigned long long pack2(float lo, float hi) {
    unsigned long long r;
    asm("mov.b64 %0, {%1, %2};" : "=l"(r) : "f"(lo), "f"(hi));
    return r;
}
__device__ __forceinline__ void unpack2(unsigned long long v, float& lo, float& hi) {
    asm("mov.b64 {%0, %1}, %2;" : "=f"(lo), "=f"(hi) : "l"(v));
}

__global__ __launch_bounds__(NTHREADS, 1)
void crf_loss_kernel(const float* __restrict__ em,
                     const int* __restrict__ tags,
                     const int* __restrict__ mask,
                     const float* __restrict__ trans,
                     const float* __restrict__ start_t,
                     const float* __restrict__ end_t,
                     float* __restrict__ out)
{
    __shared__ __align__(16) float s_p[2][NGROUPS * RSTRIDE]; // padded, double-buffered
    __shared__ float s_d[2];
    __shared__ int   s_mask[TT];
    __shared__ float s_red[NWARPS];
    __shared__ int   s_ired[NWARPS];
    __shared__ float s_num;
    __shared__ float s_seqlen;

    const int b    = blockIdx.x;
    const int tid  = threadIdx.x;
    const int lane = tid & 31;
    const int wid  = tid >> 5;
    const int jb   = tid >> 3;        // 0..47 : block of 4 columns
    const int grp  = tid & 7;         // 0..7  : row group (24 rows)
    const int jown = jb * 4 + (grp >> 1);                 // column this lane co-owns
    const bool writer = ((grp & 1) == 0);
    const int sts_off = (jown / RROWS) * RSTRIDE + (jown % RROWS);

    const float* emB = em   + (size_t)b * TT * VV;
    const int*   tgB = tags + (size_t)b * TT;
    const int*   mkB = mask + (size_t)b * TT;

    // ---------------- expT tile into registers: 4 cols x 24 rows, row-pair packed ----------------
    unsigned long long col2[4 * 12];       // col2[c*12 + k] = (expT[i,j], expT[i+1,j]), i = grp*24+2k
    #pragma unroll
    for (int c = 0; c < 4; c++) {
        const int j = jb * 4 + c;
        #pragma unroll
        for (int k = 0; k < 12; k++) {
            const int i = grp * RROWS + 2 * k;
            float e0 = __expf(trans[(i    ) * VV + j]);
            float e1 = __expf(trans[(i + 1) * VV + j]);
            col2[c * 12 + k] = pack2(e0, e1);
        }
    }

    // ---------------- mask to smem ----------------
    for (int t = tid; t < TT; t += NTHREADS) s_mask[t] = mkB[t];

    // ---------------- gold score + mask sum ----------------
    float gsum = 0.f;
    int   msum = 0;
    for (int t = tid; t < TT; t += NTHREADS) {
        int mk = mkB[t];
        msum += mk;
        if (t >= 1 && mk) {
            int tg = tgB[t];
            int tp = tgB[t - 1];
            gsum += emB[t * VV + tg] + trans[tp * VV + tg];
        }
    }
    #pragma unroll
    for (int o = 16; o > 0; o >>= 1) {
        gsum += __shfl_xor_sync(0xffffffffu, gsum, o);
        msum += __shfl_xor_sync(0xffffffffu, msum, o);
    }
    if (lane == 0) { s_red[wid] = gsum; s_ired[wid] = msum; }
    __syncthreads();
    if (tid == 0) {
        float g = 0.f; int mtot = 0;
        #pragma unroll
        for (int w = 0; w < NWARPS; w++) { g += s_red[w]; mtot += s_ired[w]; }
        int tag0  = tgB[0];
        float num = start_t[tag0] + emB[tag0] + g;
        int last  = mtot - 1; if (last < 0) last = 0;
        num += end_t[tgB[last]];
        s_num    = num;
        s_seqlen = fmaxf((float)mtot, 1.0f);
    }

    // ---------------- init: alpha0 for owned column, block max M0, p0 ----------------
    float a0 = start_t[jown] + emB[jown];
    float wm = a0;
    #pragma unroll
    for (int o = 16; o > 0; o >>= 1)
        wm = fmaxf(wm, __shfl_xor_sync(0xffffffffu, wm, o));
    __syncthreads();                       // protect s_red (tid0 still reading above)
    if (lane == 0) s_red[wid] = wm;
    __syncthreads();
    float M = s_red[0];
    #pragma unroll
    for (int w = 1; w < NWARPS; w++) M = fmaxf(M, s_red[w]);

    float p_reg = __expf(a0 - M);
    if (writer) s_p[0][sts_off] = p_reg;
    if (tid == 0) s_d[0] = a0 - M;

    float emit_next = emB[VV + jown];

    // thread-0 normalizer-estimator state
    float lr_prev = 0.f, d_prev = 0.f, beta0 = a0 - M;

    // ---------------- forward recursion: ONE sync per step ----------------
    #pragma unroll 2
    for (int t = 1; t < TT; t++) {
        const int cur = (t - 1) & 1, nxt = t & 1;
        __syncthreads();

        const float d      = s_d[cur];
        const int   mk     = s_mask[t];
        const float emit_c = emit_next;
        const float w_emit = __expf(emit_c - d);   // off critical path
        const float w_keep = __expf(-d);
        {
            int tn = (t + 1 < TT) ? (t + 1) : (TT - 1);
            emit_next = emB[tn * VV + jown];
        }

        // 4-col x 24-row matvec tile, packed over row pairs
        const double2* p2 = (const double2*)(s_p[cur] + grp * RSTRIDE);
        unsigned long long ac0 = 0ull, ac1 = 0ull, ac2 = 0ull, ac3 = 0ull;
        #pragma unroll
        for (int q = 0; q < 6; q++) {
            double2 v = p2[q];
            unsigned long long vx = __double_as_longlong(v.x);  // rows 4q, 4q+1
            unsigned long long vy = __double_as_longlong(v.y);  // rows 4q+2, 4q+3
            ffma2(ac0, vx, col2[0 * 12 + 2 * q]); ffma2(ac0, vy, col2[0 * 12 + 2 * q + 1]);
            ffma2(ac1, vx, col2[1 * 12 + 2 * q]); ffma2(ac1, vy, col2[1 * 12 + 2 * q + 1]);
            ffma2(ac2, vx, col2[2 * 12 + 2 * q]); ffma2(ac2, vy, col2[2 * 12 + 2 * q + 1]);
            ffma2(ac3, vx, col2[3 * 12 + 2 * q]); ffma2(ac3, vy, col2[3 * 12 + 2 * q + 1]);
        }
        float l, hgh;
        unpack2(ac0, l, hgh); float v0 = l + hgh;
        unpack2(ac1, l, hgh); float v1 = l + hgh;
        unpack2(ac2, l, hgh); float v2 = l + hgh;
        unpack2(ac3, l, hgh); float v3 = l + hgh;

        // reduce-scatter across the 8 row-groups (lanes grp 0..7)
        const bool g4 = (grp & 4), g2 = (grp & 2);
        float x0 = g4 ? v0 : v2;
        float x1 = g4 ? v1 : v3;
        float t0 = __shfl_xor_sync(0xffffffffu, x0, 4);
        float t1 = __shfl_xor_sync(0xffffffffu, x1, 4);
        float ra = (g4 ? v2 : v0) + t0;     // col (2*(grp>>2)+0) of this jb-half
        float rb = (g4 ? v3 : v1) + t1;
        float y  = g2 ? ra : rb;
        float t2 = __shfl_xor_sync(0xffffffffu, y, 2);
        float rc = (g2 ? rb : ra) + t2;
        float t3 = __shfl_xor_sync(0xffffffffu, rc, 1);
        float s  = rc + t3;                 // full sum for column jown

        float p_new = mk ? (s * w_emit) : (p_reg * w_keep);
        p_reg = p_new;
        M += d;
        if (writer) s_p[nxt][sts_off] = p_new;

        if (tid == 0) {   // column 0 lives here (jb=0, grp=0)
            float lr = __logf(s) + emit_c;
            beta0 = mk ? (lr - d) : (beta0 - d);
            float g_est = lr - lr_prev + d_prev;
            s_d[nxt] = beta0 + g_est;
            lr_prev = lr; d_prev = d;
        }
    }

    // ---------------- final lse(alpha + end_trans) ----------------
    __syncthreads();
    float beta = __logf(p_reg);
    float v = writer ? (beta + end_t[jown]) : -3.0e38f;
    float wm2 = v;
    #pragma unroll
    for (int o = 16; o > 0; o >>= 1)
        wm2 = fmaxf(wm2, __shfl_xor_sync(0xffffffffu, wm2, o));
    if (lane == 0) s_red[wid] = wm2;
    __syncthreads();
    float m2 = s_red[0];
    #pragma unroll
    for (int w = 1; w < NWARPS; w++) m2 = fmaxf(m2, s_red[w]);

    float e = writer ? __expf(v - m2) : 0.f;
    #pragma unroll
    for (int o = 16; o > 0; o >>= 1)
        e += __shfl_xor_sync(0xffffffffu, e, o);
    __syncthreads();
    if (lane == 0) s_red[wid] = e;
    __syncthreads();

    if (tid == 0) {
        float ssum = 0.f;
        #pragma unroll
        for (int w = 0; w < NWARPS; w++) ssum += s_red[w];
        float logden = M + m2 + logf(ssum + 1e-8f);
        out[b] = (logden - s_num) / s_seqlen;
    }
}

extern "C" void kernel_launch(void* const* d_in, const int* in_sizes, int n_in,
                              void* d_out, int out_size)
{
    const float* em    = (const float*)d_in[0];
    const int*   tags  = (const int*)d_in[1];
    const int*   mask  = (const int*)d_in[2];
    const float* trans = (const float*)d_in[3];
    const float* st    = (const float*)d_in[4];
    const float* en    = (const float*)d_in[5];
    float* out = (float*)d_out;

    crf_loss_kernel<<<BB, NTHREADS>>>(em, tags, mask, trans, st, en, out);
}

// round 5
// speedup vs baseline: 1.5484x; 1.0478x over previous
#include <cuda_runtime.h>

#define BB 128
#define TT 1024
#define VV 192
#define NTHREADS 384
#define NWARPS 12
#define NGROUPS 4
#define RROWS 48          // rows per group
#define RSTRIDE 52        // padded region stride in floats (208B: group addrs hit disjoint bank quads)

__device__ __forceinline__ void ffma2(unsigned long long& acc,
                                      unsigned long long a, unsigned long long b) {
    asm("fma.rn.f32x2 %0, %1, %2, %0;" : "+l"(acc) : "l"(a), "l"(b));
}
__device__ __forceinline__ unsigned long long pack2(float lo, float hi) {
    unsigned long long r;
    asm("mov.b64 %0, {%1, %2};" : "=l"(r) : "f"(lo), "f"(hi));
    return r;
}
__device__ __forceinline__ void unpack2(unsigned long long v, float& lo, float& hi) {
    asm("mov.b64 {%0, %1}, %2;" : "=f"(lo), "=f"(hi) : "l"(v));
}

__global__ __launch_bounds__(NTHREADS, 1)
void crf_loss_kernel(const float* __restrict__ em,
                     const int* __restrict__ tags,
                     const int* __restrict__ mask,
                     const float* __restrict__ trans,
                     const float* __restrict__ start_t,
                     const float* __restrict__ end_t,
                     float* __restrict__ out)
{
    __shared__ __align__(16) float s_p[2][NGROUPS * RSTRIDE]; // padded, double-buffered
    __shared__ float s_d[2];
    __shared__ int   s_mask[TT];
    __shared__ float s_red[NWARPS];
    __shared__ int   s_ired[NWARPS];
    __shared__ float s_num;
    __shared__ float s_seqlen;

    const int b    = blockIdx.x;
    const int tid  = threadIdx.x;
    const int lane = tid & 31;
    const int wid  = tid >> 5;
    const int jb   = tid >> 2;        // 0..95 : block of 2 columns
    const int grp  = tid & 3;         // 0..3  : row group (48 rows)
    const int jown = jb * 2 + (grp >> 1);           // column this lane co-owns
    const bool writer = ((grp & 1) == 0);
    const int sts_off = (jown / RROWS) * RSTRIDE + (jown % RROWS);

    const float* emB = em   + (size_t)b * TT * VV;
    const int*   tgB = tags + (size_t)b * TT;
    const int*   mkB = mask + (size_t)b * TT;

    // ---------------- expT tile into registers: 2 cols x 48 rows, row-pair packed ----------------
    unsigned long long col2[2 * 24];   // col2[c*24+k] = (expT[i,j], expT[i+1,j]), i = grp*48+2k
    #pragma unroll
    for (int c = 0; c < 2; c++) {
        const int j = jb * 2 + c;
        #pragma unroll
        for (int k = 0; k < 24; k++) {
            const int i = grp * RROWS + 2 * k;
            float e0 = __expf(trans[(i    ) * VV + j]);
            float e1 = __expf(trans[(i + 1) * VV + j]);
            col2[c * 24 + k] = pack2(e0, e1);
        }
    }

    // ---------------- mask to smem ----------------
    for (int t = tid; t < TT; t += NTHREADS) s_mask[t] = mkB[t];

    // ---------------- gold score + mask sum ----------------
    float gsum = 0.f;
    int   msum = 0;
    for (int t = tid; t < TT; t += NTHREADS) {
        int mk = mkB[t];
        msum += mk;
        if (t >= 1 && mk) {
            int tg = tgB[t];
            int tp = tgB[t - 1];
            gsum += emB[t * VV + tg] + trans[tp * VV + tg];
        }
    }
    #pragma unroll
    for (int o = 16; o > 0; o >>= 1) {
        gsum += __shfl_xor_sync(0xffffffffu, gsum, o);
        msum += __shfl_xor_sync(0xffffffffu, msum, o);
    }
    if (lane == 0) { s_red[wid] = gsum; s_ired[wid] = msum; }
    __syncthreads();
    if (tid == 0) {
        float g = 0.f; int mtot = 0;
        #pragma unroll
        for (int w = 0; w < NWARPS; w++) { g += s_red[w]; mtot += s_ired[w]; }
        int tag0  = tgB[0];
        float num = start_t[tag0] + emB[tag0] + g;
        int last  = mtot - 1; if (last < 0) last = 0;
        num += end_t[tgB[last]];
        s_num    = num;
        s_seqlen = fmaxf((float)mtot, 1.0f);
    }

    // ---------------- init: alpha0 for owned column, block max M0, p0 ----------------
    float a0 = start_t[jown] + emB[jown];
    float wm = a0;
    #pragma unroll
    for (int o = 16; o > 0; o >>= 1)
        wm = fmaxf(wm, __shfl_xor_sync(0xffffffffu, wm, o));
    __syncthreads();                       // protect s_red (tid0 reading above)
    if (lane == 0) s_red[wid] = wm;
    __syncthreads();
    float M = s_red[0];
    #pragma unroll
    for (int w = 1; w < NWARPS; w++) M = fmaxf(M, s_red[w]);

    float p_reg = __expf(a0 - M);
    if (writer) s_p[0][sts_off] = p_reg;
    if (tid == 0) s_d[0] = a0 - M;

    // emission prefetch, depth 2
    float e_n1 = emB[VV + jown];                       // t = 1
    float e_n2 = emB[2 * VV + jown];                   // t = 2

    // thread-0 normalizer-estimator state
    float lr_prev = 0.f, d_prev = 0.f, beta0 = a0 - M;

    // ---------------- forward recursion: ONE sync per step ----------------
    #pragma unroll 2
    for (int t = 1; t < TT; t++) {
        const int cur = (t - 1) & 1, nxt = t & 1;
        __syncthreads();

        const float d      = s_d[cur];
        const int   mk     = s_mask[t];
        const float emit_c = e_n1;
        e_n1 = e_n2;
        {
            int tn = (t + 2 < TT) ? (t + 2) : (TT - 1);
            e_n2 = emB[tn * VV + jown];
        }
        // single exp, selected argument (off critical path)
        const float arg = mk ? (emit_c - d) : (-d);
        const float w_f = __expf(arg);

        // 2-col x 48-row matvec tile, packed over row pairs
        const double2* p2 = (const double2*)(s_p[cur] + grp * RSTRIDE);
        unsigned long long ac0 = 0ull, ac1 = 0ull, ac2 = 0ull, ac3 = 0ull;
        #pragma unroll
        for (int q = 0; q < 12; q++) {
            double2 v = p2[q];
            unsigned long long vx = __double_as_longlong(v.x);  // rows 4q, 4q+1
            unsigned long long vy = __double_as_longlong(v.y);  // rows 4q+2, 4q+3
            ffma2(ac0, vx, col2[2 * q]);      ffma2(ac1, vy, col2[2 * q + 1]);
            ffma2(ac2, vx, col2[24 + 2 * q]); ffma2(ac3, vy, col2[24 + 2 * q + 1]);
        }
        float l, hh;
        unpack2(ac0, l, hh); float v0 = l + hh;
        unpack2(ac1, l, hh); v0 += (l + hh);
        unpack2(ac2, l, hh); float v1 = l + hh;
        unpack2(ac3, l, hh); v1 += (l + hh);

        // 2-stage reduce-scatter across the 4 row-groups
        float x   = (grp & 2) ? v0 : v1;
        float tsh = __shfl_xor_sync(0xffffffffu, x, 2);
        float r   = ((grp & 2) ? v1 : v0) + tsh;   // col jown, half-sum
        float t2  = __shfl_xor_sync(0xffffffffu, r, 1);
        float s   = r + t2;                        // full sum for column jown

        float p_new = (mk ? s : p_reg) * w_f;
        p_reg = p_new;
        M += d;
        if (writer) s_p[nxt][sts_off] = p_new;

        if (tid == 0) {   // column 0 lives here (jb=0, grp=0)
            float lr = __logf(s) + emit_c;
            beta0 = mk ? (lr - d) : (beta0 - d);
            float g_est = lr - lr_prev + d_prev;
            s_d[nxt] = beta0 + g_est;
            lr_prev = lr; d_prev = d;
        }
    }

    // ---------------- final lse(alpha + end_trans) ----------------
    __syncthreads();
    float beta = __logf(p_reg);
    float v = writer ? (beta + end_t[jown]) : -3.0e38f;
    float wm2 = v;
    #pragma unroll
    for (int o = 16; o > 0; o >>= 1)
        wm2 = fmaxf(wm2, __shfl_xor_sync(0xffffffffu, wm2, o));
    if (lane == 0) s_red[wid] = wm2;
    __syncthreads();
    float m2 = s_red[0];
    #pragma unroll
    for (int w = 1; w < NWARPS; w++) m2 = fmaxf(m2, s_red[w]);

    float e = writer ? __expf(v - m2) : 0.f;
    #pragma unroll
    for (int o = 16; o > 0; o >>= 1)
        e += __shfl_xor_sync(0xffffffffu, e, o);
    __syncthreads();
    if (lane == 0) s_red[wid] = e;
    __syncthreads();

    if (tid == 0) {
        float ssum = 0.f;
        #pragma unroll
        for (int w = 0; w < NWARPS; w++) ssum += s_red[w];
        float logden = M + m2 + logf(ssum + 1e-8f);
        out[b] = (logden - s_num) / s_seqlen;
    }
}

extern "C" void kernel_launch(void* const* d_in, const int* in_sizes, int n_in,
                              void* d_out, int out_size)
{
    const float* em    = (const float*)d_in[0];
    const int*   tags  = (const int*)d_in[1];
    const int*   mask  = (const int*)d_in[2];
    const float* trans = (const float*)d_in[3];
    const float* st    = (const float*)d_in[4];
    const float* en    = (const float*)d_in[5];
    float* out = (float*)d_out;

    crf_loss_kernel<<<BB, NTHREADS>>>(em, tags, mask, trans, st, en, out);
}